// round 1
// baseline (speedup 1.0000x reference)
#include <cuda_runtime.h>
#include <cuda_bf16.h>
#include <math_constants.h>

#define NMAX 50000
#define EMAX 1250000
#define FEAT 64
#define NCLS 10

__device__ int   g_deg[NMAX];
__device__ int   g_off[NMAX];
__device__ int   g_pos[NMAX];
__device__ int   g_srcs[EMAX];
__device__ float g_x1[(size_t)NMAX * FEAT];
__device__ int   g_is64;

// ---------------------------------------------------------------------------
// edge_index dtype detection: int64 values are all in [0, N); int32 data read
// as int64 produces huge values with overwhelming probability.
// ---------------------------------------------------------------------------
__global__ void detect_kernel(const void* ei, int n) {
    const long long* p = (const long long*)ei;
    int bad = 0;
    for (int i = threadIdx.x; i < 64; i += 32) {
        long long v = p[i];
        if (v < 0 || v >= (long long)n) bad = 1;
    }
    bad = __any_sync(0xffffffffu, bad);
    if (threadIdx.x == 0) g_is64 = bad ? 0 : 1;
}

__global__ void zero_deg_kernel(int n) {
    int i = blockIdx.x * blockDim.x + threadIdx.x;
    if (i < n) g_deg[i] = 0;
}

__global__ void hist_kernel(const void* ei, int E) {
    int e = blockIdx.x * blockDim.x + threadIdx.x;
    if (e >= E) return;
    int d;
    if (g_is64) d = (int)((const long long*)ei)[E + e];
    else        d = ((const int*)ei)[E + e];
    atomicAdd(&g_deg[d], 1);
}

// single-block exclusive scan of g_deg -> g_off, g_pos
__global__ void scan_kernel(int n) {
    __shared__ int part[1024];
    int t = threadIdx.x;
    int chunk = (n + 1023) / 1024;
    int b = t * chunk;
    int e = min(b + chunk, n);
    int s = 0;
    for (int i = b; i < e; ++i) s += g_deg[i];
    part[t] = s;
    __syncthreads();
    // Hillis-Steele inclusive scan
    for (int d = 1; d < 1024; d <<= 1) {
        int v = 0;
        if (t >= d) v = part[t - d];
        __syncthreads();
        part[t] += v;
        __syncthreads();
    }
    int running = part[t] - s;  // exclusive base for this chunk
    for (int i = b; i < e; ++i) {
        g_off[i] = running;
        g_pos[i] = running;
        running += g_deg[i];
    }
}

__global__ void scatter_kernel(const void* ei, int E) {
    int e = blockIdx.x * blockDim.x + threadIdx.x;
    if (e >= E) return;
    int s, d;
    if (g_is64) {
        const long long* p = (const long long*)ei;
        s = (int)p[e];
        d = (int)p[E + e];
    } else {
        const int* p = (const int*)ei;
        s = p[e];
        d = p[E + e];
    }
    int pos = atomicAdd(&g_pos[d], 1);
    g_srcs[pos] = s;
}

// ---------------------------------------------------------------------------
// Layer 1: warp per node.
// mean-aggregate neighbors, out = Wl@mean + b + Wr@x, L2-normalize, ReLU.
// ---------------------------------------------------------------------------
__global__ void __launch_bounds__(256) layer1_kernel(
    const float* __restrict__ feat,
    const float* __restrict__ Wl,
    const float* __restrict__ b,
    const float* __restrict__ Wr,
    int N)
{
    __shared__ float4 sW[FEAT * 32];   // sW[k*32+c] = (Wl[c][k], Wl[c+32][k], Wr[c][k], Wr[c+32][k])
    __shared__ float2 sV[8][FEAT];     // per-warp (mean[k], x[k])

    int tid = threadIdx.x;
    for (int idx = tid; idx < FEAT * 32; idx += 256) {
        int k = idx >> 5, c = idx & 31;
        sW[idx] = make_float4(Wl[c * FEAT + k], Wl[(c + 32) * FEAT + k],
                              Wr[c * FEAT + k], Wr[(c + 32) * FEAT + k]);
    }
    __syncthreads();

    int lane = tid & 31, w = tid >> 5;
    int warp_global = blockIdx.x * 8 + w;
    int nwarps = gridDim.x * 8;

    for (int i = warp_global; i < N; i += nwarps) {
        int deg  = g_deg[i];
        int base = g_off[i];
        float2 acc = make_float2(0.f, 0.f);
        for (int j0 = 0; j0 < deg; j0 += 32) {
            int m = deg - j0; if (m > 32) m = 32;
            int s = 0;
            if (lane < m) s = g_srcs[base + j0 + lane];
            #pragma unroll 4
            for (int j = 0; j < m; ++j) {
                int sj = __shfl_sync(0xffffffffu, s, j);
                float2 v = *(const float2*)(feat + (size_t)sj * FEAT + 2 * lane);
                acc.x += v.x; acc.y += v.y;
            }
        }
        float inv = 1.f / fmaxf((float)deg, 1.f);
        float2 xi = *(const float2*)(feat + (size_t)i * FEAT + 2 * lane);
        sV[w][2 * lane]     = make_float2(acc.x * inv, xi.x);
        sV[w][2 * lane + 1] = make_float2(acc.y * inv, xi.y);
        __syncwarp();

        float o0 = b[lane], o1 = b[lane + 32];
        #pragma unroll
        for (int k = 0; k < FEAT; ++k) {
            float2 v  = sV[w][k];
            float4 ww = sW[k * 32 + lane];
            o0 += ww.x * v.x + ww.z * v.y;
            o1 += ww.y * v.x + ww.w * v.y;
        }
        float ss = o0 * o0 + o1 * o1;
        #pragma unroll
        for (int d = 16; d; d >>= 1) ss += __shfl_xor_sync(0xffffffffu, ss, d);
        float innorm = 1.f / fmaxf(sqrtf(ss), 1e-12f);
        g_x1[(size_t)i * FEAT + lane]      = fmaxf(o0 * innorm, 0.f);
        g_x1[(size_t)i * FEAT + lane + 32] = fmaxf(o1 * innorm, 0.f);
        __syncwarp();
    }
}

// ---------------------------------------------------------------------------
// Layer 2: warp per node. mean-agg over g_x1, 10-wide GEMM, L2-normalize,
// log_softmax, write output.
// ---------------------------------------------------------------------------
__global__ void __launch_bounds__(256) layer2_kernel(
    const float* __restrict__ Wl,
    const float* __restrict__ b,
    const float* __restrict__ Wr,
    float* __restrict__ out,
    int N)
{
    __shared__ float2 sW[FEAT * NCLS];   // sW[k*10+c] = (Wl[c][k], Wr[c][k])
    __shared__ float2 sV[8][FEAT];

    int tid = threadIdx.x;
    for (int idx = tid; idx < FEAT * NCLS; idx += 256) {
        int k = idx / NCLS, c = idx % NCLS;
        sW[idx] = make_float2(Wl[c * FEAT + k], Wr[c * FEAT + k]);
    }
    __syncthreads();

    int lane = tid & 31, w = tid >> 5;
    int warp_global = blockIdx.x * 8 + w;
    int nwarps = gridDim.x * 8;

    for (int i = warp_global; i < N; i += nwarps) {
        int deg  = g_deg[i];
        int base = g_off[i];
        float2 acc = make_float2(0.f, 0.f);
        for (int j0 = 0; j0 < deg; j0 += 32) {
            int m = deg - j0; if (m > 32) m = 32;
            int s = 0;
            if (lane < m) s = g_srcs[base + j0 + lane];
            #pragma unroll 4
            for (int j = 0; j < m; ++j) {
                int sj = __shfl_sync(0xffffffffu, s, j);
                float2 v = *(const float2*)(g_x1 + (size_t)sj * FEAT + 2 * lane);
                acc.x += v.x; acc.y += v.y;
            }
        }
        float inv = 1.f / fmaxf((float)deg, 1.f);
        float2 xi = *(const float2*)(g_x1 + (size_t)i * FEAT + 2 * lane);
        sV[w][2 * lane]     = make_float2(acc.x * inv, xi.x);
        sV[w][2 * lane + 1] = make_float2(acc.y * inv, xi.y);
        __syncwarp();

        float o = 0.f;
        if (lane < NCLS) {
            o = b[lane];
            #pragma unroll
            for (int k = 0; k < FEAT; ++k) {
                float2 v  = sV[w][k];
                float2 ww = sW[k * NCLS + lane];
                o += ww.x * v.x + ww.y * v.y;
            }
        }
        // L2 normalize over the 10 classes
        float ss = (lane < NCLS) ? o * o : 0.f;
        #pragma unroll
        for (int d = 16; d; d >>= 1) ss += __shfl_xor_sync(0xffffffffu, ss, d);
        float innorm = 1.f / fmaxf(sqrtf(ss), 1e-12f);
        o *= innorm;
        // log_softmax over 10 classes
        float mx = (lane < NCLS) ? o : -CUDART_INF_F;
        #pragma unroll
        for (int d = 16; d; d >>= 1) mx = fmaxf(mx, __shfl_xor_sync(0xffffffffu, mx, d));
        float ex = (lane < NCLS) ? expf(o - mx) : 0.f;
        float es = ex;
        #pragma unroll
        for (int d = 16; d; d >>= 1) es += __shfl_xor_sync(0xffffffffu, es, d);
        float lse = logf(es);
        if (lane < NCLS)
            out[(size_t)i * NCLS + lane] = (o - mx) - lse;
        __syncwarp();
    }
}

extern "C" void kernel_launch(void* const* d_in, const int* in_sizes, int n_in,
                              void* d_out, int out_size) {
    const float* feat = (const float*)d_in[0];
    const void*  ei   = d_in[1];
    const float* W1l  = (const float*)d_in[2];
    const float* b1   = (const float*)d_in[3];
    const float* W1r  = (const float*)d_in[4];
    const float* W2l  = (const float*)d_in[5];
    const float* b2   = (const float*)d_in[6];
    const float* W2r  = (const float*)d_in[7];
    float* out = (float*)d_out;

    int N = in_sizes[0] / FEAT;
    int E = in_sizes[1] / 2;

    detect_kernel<<<1, 32>>>(ei, N);
    zero_deg_kernel<<<(N + 255) / 256, 256>>>(N);
    hist_kernel<<<(E + 255) / 256, 256>>>(ei, E);
    scan_kernel<<<1, 1024>>>(N);
    scatter_kernel<<<(E + 255) / 256, 256>>>(ei, E);

    int blocks = 888;  // 6 per SM; grid-stride over nodes amortizes weight loads
    layer1_kernel<<<blocks, 256>>>(feat, W1l, b1, W1r, N);
    layer2_kernel<<<blocks, 256>>>(W2l, b2, W2r, out, N);
}

// round 2
// speedup vs baseline: 1.3646x; 1.3646x over previous
#include <cuda_runtime.h>
#include <cuda_bf16.h>
#include <math_constants.h>

#define NMAX 50000
#define EMAX 1250000
#define FEAT 64
#define NCLS 10

#define SCAN_NB 250
#define SCAN_CH 200   // SCAN_NB * SCAN_CH = 50000 >= NMAX

__device__ int   g_deg[NMAX];
__device__ int   g_off[NMAX];
__device__ int   g_pos[NMAX];
__device__ int   g_srcs[EMAX];
__device__ int   g_bsum[SCAN_NB];
__device__ int   g_boff[SCAN_NB];
__device__ float g_x1[(size_t)NMAX * FEAT];
__device__ int   g_is64;

// ---------------------------------------------------------------------------
// edge_index dtype detection: int64 values are all in [0, N); int32 data read
// as int64 produces huge values with overwhelming probability.
// ---------------------------------------------------------------------------
__global__ void detect_kernel(const void* ei, int n) {
    const long long* p = (const long long*)ei;
    int bad = 0;
    for (int i = threadIdx.x; i < 64; i += 32) {
        long long v = p[i];
        if (v < 0 || v >= (long long)n) bad = 1;
    }
    bad = __any_sync(0xffffffffu, bad);
    if (threadIdx.x == 0) g_is64 = bad ? 0 : 1;
}

__global__ void zero_deg_kernel(int n) {
    int i = blockIdx.x * blockDim.x + threadIdx.x;
    if (i < n) g_deg[i] = 0;
}

__global__ void hist_kernel(const void* ei, int E) {
    int e = blockIdx.x * blockDim.x + threadIdx.x;
    if (e >= E) return;
    int d;
    if (g_is64) d = (int)((const long long*)ei)[E + e];
    else        d = ((const int*)ei)[E + e];
    atomicAdd(&g_deg[d], 1);
}

// ---------------------------------------------------------------------------
// 3-pass parallel exclusive scan of g_deg -> g_off / g_pos
// ---------------------------------------------------------------------------
__global__ void __launch_bounds__(256) scan_pass1(int n) {
    __shared__ int sh[256];
    int t = threadIdx.x;
    int idx = blockIdx.x * SCAN_CH + t;
    int v = (t < SCAN_CH && idx < n) ? g_deg[idx] : 0;
    sh[t] = v;
    __syncthreads();
    #pragma unroll
    for (int d = 128; d; d >>= 1) {
        if (t < d) sh[t] += sh[t + d];
        __syncthreads();
    }
    if (t == 0) g_bsum[blockIdx.x] = sh[0];
}

__global__ void __launch_bounds__(256) scan_pass2() {
    __shared__ int sh[256];
    int t = threadIdx.x;
    int v = (t < SCAN_NB) ? g_bsum[t] : 0;
    sh[t] = v;
    __syncthreads();
    #pragma unroll
    for (int d = 1; d < 256; d <<= 1) {
        int u = (t >= d) ? sh[t - d] : 0;
        __syncthreads();
        sh[t] += u;
        __syncthreads();
    }
    if (t < SCAN_NB) g_boff[t] = sh[t] - v;  // exclusive
}

__global__ void __launch_bounds__(256) scan_pass3(int n) {
    __shared__ int sh[256];
    int t = threadIdx.x;
    int idx = blockIdx.x * SCAN_CH + t;
    int v = (t < SCAN_CH && idx < n) ? g_deg[idx] : 0;
    sh[t] = v;
    __syncthreads();
    #pragma unroll
    for (int d = 1; d < 256; d <<= 1) {
        int u = (t >= d) ? sh[t - d] : 0;
        __syncthreads();
        sh[t] += u;
        __syncthreads();
    }
    if (t < SCAN_CH && idx < n) {
        int o = g_boff[blockIdx.x] + sh[t] - v;  // exclusive
        g_off[idx] = o;
        g_pos[idx] = o;
    }
}

__global__ void scatter_kernel(const void* ei, int E) {
    int e = blockIdx.x * blockDim.x + threadIdx.x;
    if (e >= E) return;
    int s, d;
    if (g_is64) {
        const long long* p = (const long long*)ei;
        s = (int)p[e];
        d = (int)p[E + e];
    } else {
        const int* p = (const int*)ei;
        s = p[e];
        d = p[E + e];
    }
    int pos = atomicAdd(&g_pos[d], 1);
    g_srcs[pos] = s;
}

// ---------------------------------------------------------------------------
// Layer 1: warp per node.
// mean-aggregate neighbors, out = Wl@mean + b + Wr@x, L2-normalize, ReLU.
// ---------------------------------------------------------------------------
__global__ void __launch_bounds__(256) layer1_kernel(
    const float* __restrict__ feat,
    const float* __restrict__ Wl,
    const float* __restrict__ b,
    const float* __restrict__ Wr,
    int N)
{
    __shared__ float4 sW[FEAT * 32];   // sW[k*32+c] = (Wl[c][k], Wl[c+32][k], Wr[c][k], Wr[c+32][k])
    __shared__ float2 sV[8][FEAT];     // per-warp (mean[k], x[k])

    int tid = threadIdx.x;
    for (int idx = tid; idx < FEAT * 32; idx += 256) {
        int k = idx >> 5, c = idx & 31;
        sW[idx] = make_float4(Wl[c * FEAT + k], Wl[(c + 32) * FEAT + k],
                              Wr[c * FEAT + k], Wr[(c + 32) * FEAT + k]);
    }
    __syncthreads();

    int lane = tid & 31, w = tid >> 5;
    int warp_global = blockIdx.x * 8 + w;
    int nwarps = gridDim.x * 8;

    for (int i = warp_global; i < N; i += nwarps) {
        int deg  = g_deg[i];
        int base = g_off[i];
        float2 acc = make_float2(0.f, 0.f);
        for (int j0 = 0; j0 < deg; j0 += 32) {
            int m = deg - j0; if (m > 32) m = 32;
            int s = 0;
            if (lane < m) s = g_srcs[base + j0 + lane];
            #pragma unroll 8
            for (int j = 0; j < m; ++j) {
                int sj = __shfl_sync(0xffffffffu, s, j);
                float2 v = *(const float2*)(feat + (size_t)sj * FEAT + 2 * lane);
                acc.x += v.x; acc.y += v.y;
            }
        }
        float inv = 1.f / fmaxf((float)deg, 1.f);
        float2 xi = *(const float2*)(feat + (size_t)i * FEAT + 2 * lane);
        sV[w][2 * lane]     = make_float2(acc.x * inv, xi.x);
        sV[w][2 * lane + 1] = make_float2(acc.y * inv, xi.y);
        __syncwarp();

        float o0 = b[lane], o1 = b[lane + 32];
        #pragma unroll
        for (int k = 0; k < FEAT; ++k) {
            float2 v  = sV[w][k];
            float4 ww = sW[k * 32 + lane];
            o0 += ww.x * v.x + ww.z * v.y;
            o1 += ww.y * v.x + ww.w * v.y;
        }
        float ss = o0 * o0 + o1 * o1;
        #pragma unroll
        for (int d = 16; d; d >>= 1) ss += __shfl_xor_sync(0xffffffffu, ss, d);
        float innorm = 1.f / fmaxf(sqrtf(ss), 1e-12f);
        g_x1[(size_t)i * FEAT + lane]      = fmaxf(o0 * innorm, 0.f);
        g_x1[(size_t)i * FEAT + lane + 32] = fmaxf(o1 * innorm, 0.f);
        __syncwarp();
    }
}

// ---------------------------------------------------------------------------
// Layer 2: warp per node. mean-agg over g_x1, 10-wide GEMM, L2-normalize,
// log_softmax, write output.
// ---------------------------------------------------------------------------
__global__ void __launch_bounds__(256) layer2_kernel(
    const float* __restrict__ Wl,
    const float* __restrict__ b,
    const float* __restrict__ Wr,
    float* __restrict__ out,
    int N)
{
    __shared__ float2 sW[FEAT * NCLS];   // sW[k*10+c] = (Wl[c][k], Wr[c][k])
    __shared__ float2 sV[8][FEAT];

    int tid = threadIdx.x;
    for (int idx = tid; idx < FEAT * NCLS; idx += 256) {
        int k = idx / NCLS, c = idx % NCLS;
        sW[idx] = make_float2(Wl[c * FEAT + k], Wr[c * FEAT + k]);
    }
    __syncthreads();

    int lane = tid & 31, w = tid >> 5;
    int warp_global = blockIdx.x * 8 + w;
    int nwarps = gridDim.x * 8;

    for (int i = warp_global; i < N; i += nwarps) {
        int deg  = g_deg[i];
        int base = g_off[i];
        float2 acc = make_float2(0.f, 0.f);
        for (int j0 = 0; j0 < deg; j0 += 32) {
            int m = deg - j0; if (m > 32) m = 32;
            int s = 0;
            if (lane < m) s = g_srcs[base + j0 + lane];
            #pragma unroll 8
            for (int j = 0; j < m; ++j) {
                int sj = __shfl_sync(0xffffffffu, s, j);
                float2 v = *(const float2*)(g_x1 + (size_t)sj * FEAT + 2 * lane);
                acc.x += v.x; acc.y += v.y;
            }
        }
        float inv = 1.f / fmaxf((float)deg, 1.f);
        float2 xi = *(const float2*)(g_x1 + (size_t)i * FEAT + 2 * lane);
        sV[w][2 * lane]     = make_float2(acc.x * inv, xi.x);
        sV[w][2 * lane + 1] = make_float2(acc.y * inv, xi.y);
        __syncwarp();

        float o = 0.f;
        if (lane < NCLS) {
            o = b[lane];
            #pragma unroll
            for (int k = 0; k < FEAT; ++k) {
                float2 v  = sV[w][k];
                float2 ww = sW[k * NCLS + lane];
                o += ww.x * v.x + ww.y * v.y;
            }
        }
        // L2 normalize over the 10 classes
        float ss = (lane < NCLS) ? o * o : 0.f;
        #pragma unroll
        for (int d = 16; d; d >>= 1) ss += __shfl_xor_sync(0xffffffffu, ss, d);
        float innorm = 1.f / fmaxf(sqrtf(ss), 1e-12f);
        o *= innorm;
        // log_softmax over 10 classes
        float mx = (lane < NCLS) ? o : -CUDART_INF_F;
        #pragma unroll
        for (int d = 16; d; d >>= 1) mx = fmaxf(mx, __shfl_xor_sync(0xffffffffu, mx, d));
        float ex = (lane < NCLS) ? expf(o - mx) : 0.f;
        float es = ex;
        #pragma unroll
        for (int d = 16; d; d >>= 1) es += __shfl_xor_sync(0xffffffffu, es, d);
        float lse = logf(es);
        if (lane < NCLS)
            out[(size_t)i * NCLS + lane] = (o - mx) - lse;
        __syncwarp();
    }
}

extern "C" void kernel_launch(void* const* d_in, const int* in_sizes, int n_in,
                              void* d_out, int out_size) {
    const float* feat = (const float*)d_in[0];
    const void*  ei   = d_in[1];
    const float* W1l  = (const float*)d_in[2];
    const float* b1   = (const float*)d_in[3];
    const float* W1r  = (const float*)d_in[4];
    const float* W2l  = (const float*)d_in[5];
    const float* b2   = (const float*)d_in[6];
    const float* W2r  = (const float*)d_in[7];
    float* out = (float*)d_out;

    int N = in_sizes[0] / FEAT;
    int E = in_sizes[1] / 2;

    detect_kernel<<<1, 32>>>(ei, N);
    zero_deg_kernel<<<(N + 255) / 256, 256>>>(N);
    hist_kernel<<<(E + 255) / 256, 256>>>(ei, E);
    scan_pass1<<<SCAN_NB, 256>>>(N);
    scan_pass2<<<1, 256>>>();
    scan_pass3<<<SCAN_NB, 256>>>(N);
    scatter_kernel<<<(E + 255) / 256, 256>>>(ei, E);

    int blocks = 888;  // 6 per SM; grid-stride over nodes amortizes weight loads
    layer1_kernel<<<blocks, 256>>>(feat, W1l, b1, W1r, N);
    layer2_kernel<<<blocks, 256>>>(W2l, b2, W2r, out, N);
}

// round 3
// speedup vs baseline: 1.4074x; 1.0314x over previous
#include <cuda_runtime.h>
#include <cuda_bf16.h>
#include <math_constants.h>

#define NMAX 50000
#define EMAX 1250000
#define FEAT 64
#define NCLS 10
#define NPB  4          // nodes per warp batch in the layer kernels

#define SCAN_NB 250
#define SCAN_CH 200     // SCAN_NB * SCAN_CH = 50000 >= NMAX

__device__ int   g_deg[NMAX];
__device__ int   g_off[NMAX];
__device__ int   g_pos[NMAX];
__device__ int   g_srcs[EMAX];
__device__ int   g_bsum[SCAN_NB];
__device__ int   g_boff[SCAN_NB];
__device__ float g_x1[(size_t)NMAX * FEAT];
__device__ int   g_is64;
__device__ int   g_scan_ctr;

// ---------------------------------------------------------------------------
// init: zero degree array, reset scan counter, detect edge_index dtype.
// int64 values are all in [0, N); int32 data read as int64 is garbage.
// ---------------------------------------------------------------------------
__global__ void init_kernel(const void* ei, int n) {
    int i = blockIdx.x * blockDim.x + threadIdx.x;
    if (i < n) g_deg[i] = 0;
    if (blockIdx.x == 0 && threadIdx.x < 32) {
        const long long* p = (const long long*)ei;
        int bad = 0;
        for (int j = threadIdx.x; j < 64; j += 32) {
            long long v = p[j];
            if (v < 0 || v >= (long long)n) bad = 1;
        }
        bad = __any_sync(0xffffffffu, bad);
        if (threadIdx.x == 0) { g_is64 = bad ? 0 : 1; g_scan_ctr = 0; }
    }
}

__global__ void hist_kernel(const void* ei, int E) {
    int e = blockIdx.x * blockDim.x + threadIdx.x;
    if (e >= E) return;
    int d;
    if (g_is64) d = (int)((const long long*)ei)[E + e];
    else        d = ((const int*)ei)[E + e];
    atomicAdd(&g_deg[d], 1);
}

// ---------------------------------------------------------------------------
// scan pass 1 (per-block sums) with fused pass 2 (last block scans the sums).
// Writer: write g_bsum -> __threadfence -> atomicAdd (release).
// Last block: atomicAdd observes all -> __threadfence -> read (acquire).
// ---------------------------------------------------------------------------
__global__ void __launch_bounds__(256) scan_pass12(int n) {
    __shared__ int sh[256];
    __shared__ int slast;
    int t = threadIdx.x;
    int idx = blockIdx.x * SCAN_CH + t;
    int v = (t < SCAN_CH && idx < n) ? g_deg[idx] : 0;
    sh[t] = v;
    __syncthreads();
    #pragma unroll
    for (int d = 128; d; d >>= 1) {
        if (t < d) sh[t] += sh[t + d];
        __syncthreads();
    }
    if (t == 0) {
        g_bsum[blockIdx.x] = sh[0];
        __threadfence();
        int c = atomicAdd(&g_scan_ctr, 1);
        slast = (c == gridDim.x - 1) ? 1 : 0;
    }
    __syncthreads();
    if (slast) {
        __threadfence();
        int bv = (t < SCAN_NB) ? g_bsum[t] : 0;
        sh[t] = bv;
        __syncthreads();
        #pragma unroll
        for (int d = 1; d < 256; d <<= 1) {
            int u = (t >= d) ? sh[t - d] : 0;
            __syncthreads();
            sh[t] += u;
            __syncthreads();
        }
        if (t < SCAN_NB) g_boff[t] = sh[t] - bv;  // exclusive
    }
}

__global__ void __launch_bounds__(256) scan_pass3(int n) {
    __shared__ int sh[256];
    int t = threadIdx.x;
    int idx = blockIdx.x * SCAN_CH + t;
    int v = (t < SCAN_CH && idx < n) ? g_deg[idx] : 0;
    sh[t] = v;
    __syncthreads();
    #pragma unroll
    for (int d = 1; d < 256; d <<= 1) {
        int u = (t >= d) ? sh[t - d] : 0;
        __syncthreads();
        sh[t] += u;
        __syncthreads();
    }
    if (t < SCAN_CH && idx < n) {
        int o = g_boff[blockIdx.x] + sh[t] - v;  // exclusive
        g_off[idx] = o;
        g_pos[idx] = o;
    }
}

__global__ void scatter_kernel(const void* ei, int E) {
    int e = blockIdx.x * blockDim.x + threadIdx.x;
    if (e >= E) return;
    int s, d;
    if (g_is64) {
        const long long* p = (const long long*)ei;
        s = (int)p[e];
        d = (int)p[E + e];
    } else {
        const int* p = (const int*)ei;
        s = p[e];
        d = p[E + e];
    }
    int pos = atomicAdd(&g_pos[d], 1);
    g_srcs[pos] = s;
}

// ---------------------------------------------------------------------------
// Layer 1: warp per NPB nodes. Gather NPB mean/x rows into shared, then ONE
// pass over the 128x64 weight tile computes all NPB outputs (amortizes the
// LDS.128 weight reads NPB-fold). Then bias + L2-normalize + ReLU.
// ---------------------------------------------------------------------------
__global__ void __launch_bounds__(256) layer1_kernel(
    const float* __restrict__ feat,
    const float* __restrict__ Wl,
    const float* __restrict__ b,
    const float* __restrict__ Wr,
    int N)
{
    __shared__ float4 sW[FEAT * 32];        // 32KB: (Wl[c][k],Wl[c+32][k],Wr[c][k],Wr[c+32][k])
    __shared__ float2 sV[8][NPB * FEAT];    // 16KB: per warp, NPB nodes of (mean[k], x[k])

    int tid = threadIdx.x;
    for (int idx = tid; idx < FEAT * 32; idx += 256) {
        int k = idx >> 5, c = idx & 31;
        sW[idx] = make_float4(Wl[c * FEAT + k], Wl[(c + 32) * FEAT + k],
                              Wr[c * FEAT + k], Wr[(c + 32) * FEAT + k]);
    }
    __syncthreads();

    int lane = tid & 31, w = tid >> 5;
    int warp_global = blockIdx.x * 8 + w;
    int nwarps = gridDim.x * 8;
    float bias0 = b[lane], bias1 = b[lane + 32];

    for (int i0 = warp_global * NPB; i0 < N; i0 += nwarps * NPB) {
        // ---- gather phase: NPB nodes ----
        #pragma unroll
        for (int t = 0; t < NPB; ++t) {
            int i = i0 + t;
            if (i >= N) break;
            int deg  = g_deg[i];
            int base = g_off[i];
            float2 acc = make_float2(0.f, 0.f);
            for (int j0 = 0; j0 < deg; j0 += 32) {
                int m = deg - j0; if (m > 32) m = 32;
                int s = 0;
                if (lane < m) s = g_srcs[base + j0 + lane];
                #pragma unroll 8
                for (int j = 0; j < m; ++j) {
                    int sj = __shfl_sync(0xffffffffu, s, j);
                    float2 v = *(const float2*)(feat + (size_t)sj * FEAT + 2 * lane);
                    acc.x += v.x; acc.y += v.y;
                }
            }
            float inv = 1.f / fmaxf((float)deg, 1.f);
            float2 xi = *(const float2*)(feat + (size_t)i * FEAT + 2 * lane);
            sV[w][t * FEAT + 2 * lane]     = make_float2(acc.x * inv, xi.x);
            sV[w][t * FEAT + 2 * lane + 1] = make_float2(acc.y * inv, xi.y);
        }
        __syncwarp();

        // ---- transform phase: one weight pass for NPB nodes ----
        float o0[NPB], o1[NPB];
        #pragma unroll
        for (int t = 0; t < NPB; ++t) { o0[t] = bias0; o1[t] = bias1; }
        #pragma unroll
        for (int k = 0; k < FEAT; ++k) {
            float4 ww = sW[k * 32 + lane];
            #pragma unroll
            for (int t = 0; t < NPB; ++t) {
                float2 v = sV[w][t * FEAT + k];
                o0[t] += ww.x * v.x + ww.z * v.y;
                o1[t] += ww.y * v.x + ww.w * v.y;
            }
        }
        #pragma unroll
        for (int t = 0; t < NPB; ++t) {
            int i = i0 + t;
            if (i >= N) break;
            float ss = o0[t] * o0[t] + o1[t] * o1[t];
            #pragma unroll
            for (int d = 16; d; d >>= 1) ss += __shfl_xor_sync(0xffffffffu, ss, d);
            float innorm = 1.f / fmaxf(sqrtf(ss), 1e-12f);
            g_x1[(size_t)i * FEAT + lane]      = fmaxf(o0[t] * innorm, 0.f);
            g_x1[(size_t)i * FEAT + lane + 32] = fmaxf(o1[t] * innorm, 0.f);
        }
        __syncwarp();
    }
}

// ---------------------------------------------------------------------------
// Layer 2: warp per NPB nodes over g_x1. 10-wide transform, L2-normalize,
// log_softmax.
// ---------------------------------------------------------------------------
__global__ void __launch_bounds__(256) layer2_kernel(
    const float* __restrict__ Wl,
    const float* __restrict__ b,
    const float* __restrict__ Wr,
    float* __restrict__ out,
    int N)
{
    __shared__ float2 sW[FEAT * NCLS];      // 5KB: (Wl[c][k], Wr[c][k])
    __shared__ float2 sV[8][NPB * FEAT];    // 16KB

    int tid = threadIdx.x;
    for (int idx = tid; idx < FEAT * NCLS; idx += 256) {
        int k = idx / NCLS, c = idx % NCLS;
        sW[idx] = make_float2(Wl[c * FEAT + k], Wr[c * FEAT + k]);
    }
    __syncthreads();

    int lane = tid & 31, w = tid >> 5;
    int cl = (lane < NCLS) ? lane : (NCLS - 1);   // clamped class index (lanes>=10 discarded)
    float bias = b[cl];
    int warp_global = blockIdx.x * 8 + w;
    int nwarps = gridDim.x * 8;

    for (int i0 = warp_global * NPB; i0 < N; i0 += nwarps * NPB) {
        #pragma unroll
        for (int t = 0; t < NPB; ++t) {
            int i = i0 + t;
            if (i >= N) break;
            int deg  = g_deg[i];
            int base = g_off[i];
            float2 acc = make_float2(0.f, 0.f);
            for (int j0 = 0; j0 < deg; j0 += 32) {
                int m = deg - j0; if (m > 32) m = 32;
                int s = 0;
                if (lane < m) s = g_srcs[base + j0 + lane];
                #pragma unroll 8
                for (int j = 0; j < m; ++j) {
                    int sj = __shfl_sync(0xffffffffu, s, j);
                    float2 v = *(const float2*)(g_x1 + (size_t)sj * FEAT + 2 * lane);
                    acc.x += v.x; acc.y += v.y;
                }
            }
            float inv = 1.f / fmaxf((float)deg, 1.f);
            float2 xi = *(const float2*)(g_x1 + (size_t)i * FEAT + 2 * lane);
            sV[w][t * FEAT + 2 * lane]     = make_float2(acc.x * inv, xi.x);
            sV[w][t * FEAT + 2 * lane + 1] = make_float2(acc.y * inv, xi.y);
        }
        __syncwarp();

        float o[NPB];
        #pragma unroll
        for (int t = 0; t < NPB; ++t) o[t] = bias;
        #pragma unroll
        for (int k = 0; k < FEAT; ++k) {
            float2 ww = sW[k * NCLS + cl];
            #pragma unroll
            for (int t = 0; t < NPB; ++t) {
                float2 v = sV[w][t * FEAT + k];
                o[t] += ww.x * v.x + ww.y * v.y;
            }
        }
        #pragma unroll
        for (int t = 0; t < NPB; ++t) {
            int i = i0 + t;
            if (i >= N) break;
            float ot = o[t];
            float ss = (lane < NCLS) ? ot * ot : 0.f;
            #pragma unroll
            for (int d = 16; d; d >>= 1) ss += __shfl_xor_sync(0xffffffffu, ss, d);
            float innorm = 1.f / fmaxf(sqrtf(ss), 1e-12f);
            ot *= innorm;
            float mx = (lane < NCLS) ? ot : -CUDART_INF_F;
            #pragma unroll
            for (int d = 16; d; d >>= 1) mx = fmaxf(mx, __shfl_xor_sync(0xffffffffu, mx, d));
            float ex = (lane < NCLS) ? expf(ot - mx) : 0.f;
            float es = ex;
            #pragma unroll
            for (int d = 16; d; d >>= 1) es += __shfl_xor_sync(0xffffffffu, es, d);
            float lse = logf(es);
            if (lane < NCLS)
                out[(size_t)i * NCLS + lane] = (ot - mx) - lse;
        }
        __syncwarp();
    }
}

extern "C" void kernel_launch(void* const* d_in, const int* in_sizes, int n_in,
                              void* d_out, int out_size) {
    const float* feat = (const float*)d_in[0];
    const void*  ei   = d_in[1];
    const float* W1l  = (const float*)d_in[2];
    const float* b1   = (const float*)d_in[3];
    const float* W1r  = (const float*)d_in[4];
    const float* W2l  = (const float*)d_in[5];
    const float* b2   = (const float*)d_in[6];
    const float* W2r  = (const float*)d_in[7];
    float* out = (float*)d_out;

    int N = in_sizes[0] / FEAT;
    int E = in_sizes[1] / 2;

    init_kernel<<<(N + 255) / 256, 256>>>(ei, N);
    hist_kernel<<<(E + 255) / 256, 256>>>(ei, E);
    scan_pass12<<<SCAN_NB, 256>>>(N);
    scan_pass3<<<SCAN_NB, 256>>>(N);
    scatter_kernel<<<(E + 255) / 256, 256>>>(ei, E);

    int blocks = 592;   // 4 blocks/SM (48KB smem) x 148 SMs
    layer1_kernel<<<blocks, 256>>>(feat, W1l, b1, W1r, N);
    layer2_kernel<<<blocks, 256>>>(W2l, b2, W2r, out, N);
}